// round 5
// baseline (speedup 1.0000x reference)
#include <cuda_runtime.h>

// Shapes: seq=64 steps (orig B), only batch-row t=255 of T=256 matters.
#define STEPS 64
#define HID   1024
#define G4    4096
#define TT    256
#define DD    1024
#define CC    27
#define NB    128   // recurrence CTAs (1 per SM, co-resident)

typedef unsigned long long ull;

// ---- scratch (device globals; no allocation) ----
__device__ float g_xgp[4L * STEPS * G4];   // GEMM K-split partials
__device__ float g_h1 [STEPS * HID];
__device__ float g_h2 [STEPS * HID];
__device__ float g_zp [4 * STEPS * 512];   // fc1 partials
__device__ int   g_flag[2 * STEPS * NB];   // per-CTA per-step barrier flags

__global__ void reset_kernel() {
    int i = blockIdx.x * 256 + threadIdx.x;
    if (i < 2 * STEPS * NB) g_flag[i] = 0;
}

__device__ __forceinline__ float sigf(float x)  { return 1.0f / (1.0f + __expf(-x)); }
__device__ __forceinline__ float tanhfast(float x) { return 2.0f / (1.0f + __expf(-2.0f * x)) - 1.0f; }

__device__ __forceinline__ ull fma2(ull a, ull b, ull c) {
    ull d;
    asm("fma.rn.f32x2 %0, %1, %2, %3;" : "=l"(d) : "l"(a), "l"(b), "l"(c));
    return d;
}
__device__ __forceinline__ float2 unpack2(ull v) {
    float2 f;
    asm("mov.b64 {%0, %1}, %2;" : "=f"(f.x), "=f"(f.y) : "l"(v));
    return f;
}
__device__ __forceinline__ void st_release(int* p, int v) {
    asm volatile("st.release.gpu.global.s32 [%0], %1;" :: "l"(p), "r"(v) : "memory");
}
__device__ __forceinline__ int ld_relaxed(const int* p) {
    int v;
    asm volatile("ld.relaxed.gpu.global.s32 %0, [%1];" : "=r"(v) : "l"(p) : "memory");
    return v;
}

// ============================================================
// K-split tiled GEMM (partials only):
//   mode 0: X = x[:,255,:] (stride T*D), rows=4096 -> g_xgp
//   mode 1: X = g_h1,                    rows=4096 -> g_xgp
//   mode 2: X = g_h2,                    rows=512  -> g_zp
// ============================================================
__global__ __launch_bounds__(128)
void gemm4_k(int mode, const float* __restrict__ xin, const float* __restrict__ W)
{
    __shared__ __align__(16) float Ws[32][36];
    __shared__ __align__(16) float Xs[32][68];

    const float* X;
    long xbase, xstride;
    float* pout;
    int nrows, ntiles;
    if (mode == 0)      { X = xin;  xbase = 255L * DD; xstride = (long)TT * DD; pout = g_xgp; nrows = G4;  ntiles = 128; }
    else if (mode == 1) { X = g_h1; xbase = 0;         xstride = HID;           pout = g_xgp; nrows = G4;  ntiles = 128; }
    else                { X = g_h2; xbase = 0;         xstride = HID;           pout = g_zp;  nrows = 512; ntiles = 16;  }

    const int chunk = blockIdx.x / ntiles;
    const int rb    = (blockIdx.x % ntiles) * 32;
    pout += (long)chunk * STEPS * nrows;

    const int t  = threadIdx.x;
    const int tr = t >> 4;
    const int tc = t & 15;

    float acc[4][4];
#pragma unroll
    for (int i = 0; i < 4; i++)
#pragma unroll
        for (int j = 0; j < 4; j++) acc[i][j] = 0.0f;

    const int k0 = chunk * 256;
    for (int kt = k0; kt < k0 + 256; kt += 32) {
#pragma unroll
        for (int i = 0; i < 8; i++) {
            int e = t + i * 128;
            int r = e >> 5, k = e & 31;
            Ws[k][r] = W[(long)(rb + r) * 1024 + kt + k];
        }
#pragma unroll
        for (int i = 0; i < 16; i++) {
            int e = t + i * 128;
            int s = e >> 5, k = e & 31;
            Xs[k][s] = X[xbase + (long)s * xstride + kt + k];
        }
        __syncthreads();
#pragma unroll
        for (int k = 0; k < 32; k++) {
            float4 wv = *(const float4*)&Ws[k][tr * 4];
            float4 xv = *(const float4*)&Xs[k][tc * 4];
            acc[0][0] = fmaf(wv.x, xv.x, acc[0][0]);
            acc[0][1] = fmaf(wv.x, xv.y, acc[0][1]);
            acc[0][2] = fmaf(wv.x, xv.z, acc[0][2]);
            acc[0][3] = fmaf(wv.x, xv.w, acc[0][3]);
            acc[1][0] = fmaf(wv.y, xv.x, acc[1][0]);
            acc[1][1] = fmaf(wv.y, xv.y, acc[1][1]);
            acc[1][2] = fmaf(wv.y, xv.z, acc[1][2]);
            acc[1][3] = fmaf(wv.y, xv.w, acc[1][3]);
            acc[2][0] = fmaf(wv.z, xv.x, acc[2][0]);
            acc[2][1] = fmaf(wv.z, xv.y, acc[2][1]);
            acc[2][2] = fmaf(wv.z, xv.z, acc[2][2]);
            acc[2][3] = fmaf(wv.z, xv.w, acc[2][3]);
            acc[3][0] = fmaf(wv.w, xv.x, acc[3][0]);
            acc[3][1] = fmaf(wv.w, xv.y, acc[3][1]);
            acc[3][2] = fmaf(wv.w, xv.z, acc[3][2]);
            acc[3][3] = fmaf(wv.w, xv.w, acc[3][3]);
        }
        __syncthreads();
    }

#pragma unroll
    for (int i = 0; i < 4; i++) {
        int row = rb + tr * 4 + i;
#pragma unroll
        for (int j = 0; j < 4; j++)
            pout[(long)(tc * 4 + j) * nrows + row] = acc[i][j];
    }
}

// ============================================================
// Persistent LSTM recurrence. 128 CTAs x 256 threads.
// - Whh rows in registers as packed f32x2 (fma.rn.f32x2)
// - xg = sum of 4 GEMM partials + bias, loaded by lane 0 (hidden under poll)
// - grid barrier: per-CTA release flags + warp-0 relaxed poll + acquire fence
// ============================================================
__global__ __launch_bounds__(256, 1)
void lstm_rec(const float* __restrict__ Whh,
              const float* __restrict__ ba, const float* __restrict__ bb,
              int layer)
{
    __shared__ __align__(16) float hsh[HID];
    __shared__ float graw[32];   // [unit*4 + gate]
    __shared__ float gact[32];

    float* hseq = layer ? g_h2 : g_h1;
    const int r    = blockIdx.x;
    const int t    = threadIdx.x;
    const int lane = t & 31;
    const int w    = t >> 5;
    const int g    = w & 3;
    const int jh   = w >> 2;
    const int rowbase = (g << 10) + (r << 3) + (jh << 2);
    const int fbase   = layer * STEPS * NB;

    // packed weights: w{q}[p] covers columns p*64 + lane*2 + {0,1} of row rowbase+q
    ull w0[16], w1[16], w2[16], w3[16];
#pragma unroll
    for (int p = 0; p < 16; p++) {
        long o = (long)rowbase * 1024 + p * 64 + lane * 2;
        w0[p] = *(const ull*)(Whh + o);
        w1[p] = *(const ull*)(Whh + o + 1024);
        w2[p] = *(const ull*)(Whh + o + 2048);
        w3[p] = *(const ull*)(Whh + o + 3072);
    }
    float4 bias = make_float4(0.f, 0.f, 0.f, 0.f);
    if (lane == 0) {
        bias.x = ba[rowbase]     + bb[rowbase];
        bias.y = ba[rowbase + 1] + bb[rowbase + 1];
        bias.z = ba[rowbase + 2] + bb[rowbase + 2];
        bias.w = ba[rowbase + 3] + bb[rowbase + 3];
    }
    float creg = 0.0f;   // cell state, valid for warp 0 lanes < 8
    __syncthreads();

    for (int s = 0; s < STEPS; s++) {
        // input-gate contributions: 4 partials + bias (lane 0 per warp, hidden under poll)
        float4 xq = bias;
        if (lane == 0) {
            long b = (long)s * G4 + rowbase;
            float4 p0 = *(const float4*)&g_xgp[b];
            float4 p1 = *(const float4*)&g_xgp[b + 1L * STEPS * G4];
            float4 p2 = *(const float4*)&g_xgp[b + 2L * STEPS * G4];
            float4 p3 = *(const float4*)&g_xgp[b + 3L * STEPS * G4];
            xq.x += p0.x + p1.x + p2.x + p3.x;
            xq.y += p0.y + p1.y + p2.y + p3.y;
            xq.z += p0.z + p1.z + p2.z + p3.z;
            xq.w += p0.w + p1.w + p2.w + p3.w;
        }

        float a0 = 0.f, a1 = 0.f, a2 = 0.f, a3 = 0.f;
        if (s > 0) {
            // wait for all CTAs' step s-1 flags (distinct addresses -> no LTS serialization)
            if (w == 0) {
                const int* fp = &g_flag[fbase + (s - 1) * NB + lane * 4];
                for (;;) {
                    int v0 = ld_relaxed(fp);
                    int v1 = ld_relaxed(fp + 1);
                    int v2 = ld_relaxed(fp + 2);
                    int v3 = ld_relaxed(fp + 3);
                    if (__all_sync(0xffffffffu, v0 & v1 & v2 & v3)) break;
                }
                asm volatile("fence.acq_rel.gpu;" ::: "memory");
            }
            __syncthreads();

            // stage h_{s-1} into smem (L1 bypass: produced by other SMs)
            float4 hv = __ldcg((const float4*)(hseq + (s - 1) * HID) + t);
            ((float4*)hsh)[t] = hv;
            __syncthreads();

            ull acc0 = 0ull, acc1 = 0ull, acc2 = 0ull, acc3 = 0ull;
#pragma unroll
            for (int p = 0; p < 16; p++) {
                ull h2 = *(const ull*)&hsh[p * 64 + lane * 2];
                acc0 = fma2(w0[p], h2, acc0);
                acc1 = fma2(w1[p], h2, acc1);
                acc2 = fma2(w2[p], h2, acc2);
                acc3 = fma2(w3[p], h2, acc3);
            }
            float2 f0 = unpack2(acc0), f1 = unpack2(acc1), f2 = unpack2(acc2), f3 = unpack2(acc3);
            a0 = f0.x + f0.y; a1 = f1.x + f1.y; a2 = f2.x + f2.y; a3 = f3.x + f3.y;
        }
#pragma unroll
        for (int o = 16; o > 0; o >>= 1) {
            a0 += __shfl_down_sync(0xffffffffu, a0, o);
            a1 += __shfl_down_sync(0xffffffffu, a1, o);
            a2 += __shfl_down_sync(0xffffffffu, a2, o);
            a3 += __shfl_down_sync(0xffffffffu, a3, o);
        }
        if (lane == 0) {
            graw[(jh * 4 + 0) * 4 + g] = a0 + xq.x;
            graw[(jh * 4 + 1) * 4 + g] = a1 + xq.y;
            graw[(jh * 4 + 2) * 4 + g] = a2 + xq.z;
            graw[(jh * 4 + 3) * 4 + g] = a3 + xq.w;
        }
        __syncthreads();

        if (w == 0) {
            // parallel activations: lane = unit*4 + gate
            float v = graw[lane];
            gact[lane] = ((lane & 3) == 2) ? tanhfast(v) : sigf(v);
            __syncwarp();
            if (lane < 8) {
                float iv = gact[lane * 4 + 0];
                float fv = gact[lane * 4 + 1];
                float gv = gact[lane * 4 + 2];
                float ov = gact[lane * 4 + 3];
                creg = fmaf(fv, creg, iv * gv);
                hseq[s * HID + r * 8 + lane] = ov * tanhfast(creg);
            }
            __syncwarp();
            if (lane == 0) st_release(&g_flag[fbase + s * NB + r], 1);
        }
        __syncthreads();   // keep other warps from racing into hsh rewrite before warp 0 reads graw
    }
}

// ============================================================
// FC2 fused with fc1 partial-reduce + bias + ReLU. One CTA per s.
// ============================================================
__global__ __launch_bounds__(128)
void fc2_k(const float* __restrict__ W2, const float* __restrict__ b2,
           const float* __restrict__ b1, float* __restrict__ out)
{
    __shared__ __align__(16) float zsh[512];
    const int s = blockIdx.x;
    const int t = threadIdx.x, lane = t & 31, w = t >> 5;

    {
        const long base = (long)s * 512 + t * 4;
        float4 p0 = *(const float4*)&g_zp[base];
        float4 p1 = *(const float4*)&g_zp[base + 1L * STEPS * 512];
        float4 p2 = *(const float4*)&g_zp[base + 2L * STEPS * 512];
        float4 p3 = *(const float4*)&g_zp[base + 3L * STEPS * 512];
        float4 vb = *(const float4*)&b1[t * 4];
        float4 z;
        z.x = fmaxf(p0.x + p1.x + p2.x + p3.x + vb.x, 0.f);
        z.y = fmaxf(p0.y + p1.y + p2.y + p3.y + vb.y, 0.f);
        z.z = fmaxf(p0.z + p1.z + p2.z + p3.z + vb.z, 0.f);
        z.w = fmaxf(p0.w + p1.w + p2.w + p3.w + vb.w, 0.f);
        *(float4*)&zsh[t * 4] = z;
    }
    __syncthreads();

    for (int c = w; c < CC; c += 4) {
        float acc = 0.f;
#pragma unroll
        for (int k = 0; k < 16; k++)
            acc = fmaf(zsh[k * 32 + lane], W2[c * 512 + k * 32 + lane], acc);
#pragma unroll
        for (int o = 16; o > 0; o >>= 1)
            acc += __shfl_down_sync(0xffffffffu, acc, o);
        if (lane == 0) out[s * CC + c] = acc + b2[c];
    }
}

// ============================================================
extern "C" void kernel_launch(void* const* d_in, const int* in_sizes, int n_in,
                              void* d_out, int out_size)
{
    const float* x    = (const float*)d_in[0];
    const float* Wih0 = (const float*)d_in[1];
    const float* Whh0 = (const float*)d_in[2];
    const float* bih0 = (const float*)d_in[3];
    const float* bhh0 = (const float*)d_in[4];
    const float* Wih1 = (const float*)d_in[5];
    const float* Whh1 = (const float*)d_in[6];
    const float* bih1 = (const float*)d_in[7];
    const float* bhh1 = (const float*)d_in[8];
    const float* W1   = (const float*)d_in[9];
    const float* b1   = (const float*)d_in[10];
    const float* W2   = (const float*)d_in[11];
    const float* b2   = (const float*)d_in[12];
    float* out = (float*)d_out;

    reset_kernel<<<64, 256>>>();
    gemm4_k<<<512, 128>>>(0, x, Wih0);
    lstm_rec<<<NB, 256>>>(Whh0, bih0, bhh0, 0);
    gemm4_k<<<512, 128>>>(1, nullptr, Wih1);
    lstm_rec<<<NB, 256>>>(Whh1, bih1, bhh1, 1);
    gemm4_k<<<64, 128>>>(2, nullptr, W1);
    fc2_k<<<64, 128>>>(W2, b2, b1, out);
}

// round 7
// speedup vs baseline: 1.5238x; 1.5238x over previous
#include <cuda_runtime.h>

// Shapes: seq=64 steps (orig B), only batch-row t=255 of T=256 matters.
#define STEPS 64
#define HID   1024
#define G4    4096
#define TT    256
#define DD    1024
#define CC    27
#define NB    128        // recurrence CTAs (1/SM, co-resident)
#define NCH   8          // GEMM K-split chunks
#define KC    128        // k per chunk
#define SENT  0xFFC0DEADu  // NaN payload: impossible LSTM output bit pattern

typedef unsigned long long ull;
typedef unsigned int uint;

// ---- scratch (device globals; no allocation) ----
__device__ __align__(16) float g_xgp[(long)NCH * STEPS * G4];  // gate-preact partials
__device__ __align__(16) float g_h1 [STEPS * HID];
__device__ __align__(16) float g_h2 [STEPS * HID];
__device__ __align__(16) float g_zp [NCH * STEPS * 512];       // fc1 partials

// pre-fill h buffers with sentinel (data-as-flag barrier)
__global__ void reset_kernel() {
    int i = blockIdx.x * 256 + threadIdx.x;   // 256x256 = 65536 = STEPS*HID
    ((uint*)g_h1)[i] = SENT;
    ((uint*)g_h2)[i] = SENT;
}

__device__ __forceinline__ float sigf(float x)     { return 1.0f / (1.0f + __expf(-x)); }
__device__ __forceinline__ float tanhfast(float x) { return 2.0f / (1.0f + __expf(-2.0f * x)) - 1.0f; }

__device__ __forceinline__ ull fma2(ull a, ull b, ull c) {
    ull d;
    asm("fma.rn.f32x2 %0, %1, %2, %3;" : "=l"(d) : "l"(a), "l"(b), "l"(c));
    return d;
}
__device__ __forceinline__ float2 unpack2(ull v) {
    float2 f;
    asm("mov.b64 {%0, %1}, %2;" : "=f"(f.x), "=f"(f.y) : "l"(v));
    return f;
}
// morally-strong relaxed atomics (gpu scope) for the racing h exchange
__device__ __forceinline__ uint ld_relaxed_u32(const uint* p) {
    uint v;
    asm volatile("ld.relaxed.gpu.global.u32 %0, [%1];" : "=r"(v) : "l"(p) : "memory");
    return v;
}
__device__ __forceinline__ void st_relaxed_f32(float* p, float v) {
    asm volatile("st.relaxed.gpu.global.f32 [%0], %1;" :: "l"(p), "f"(v) : "memory");
}

// ============================================================
// K-split (x8) tiled GEMM, float4 global loads, partials only:
//   mode 0: X = x[:,255,:] (stride T*D), rows=4096 -> g_xgp   grid 1024
//   mode 1: X = g_h1,                    rows=4096 -> g_xgp   grid 1024
//   mode 2: X = g_h2,                    rows=512  -> g_zp    grid 128
// ============================================================
__global__ __launch_bounds__(128)
void gemm8_k(int mode, const float* __restrict__ xin, const float* __restrict__ W)
{
    __shared__ __align__(16) float Ws[32][36];
    __shared__ __align__(16) float Xs[32][68];

    const float* X;
    long xbase, xstride;
    float* pout;
    int nrows, ntiles;
    if (mode == 0)      { X = xin;  xbase = 255L * DD; xstride = (long)TT * DD; pout = g_xgp; nrows = G4;  ntiles = 128; }
    else if (mode == 1) { X = g_h1; xbase = 0;         xstride = HID;           pout = g_xgp; nrows = G4;  ntiles = 128; }
    else                { X = g_h2; xbase = 0;         xstride = HID;           pout = g_zp;  nrows = 512; ntiles = 16;  }

    const int chunk = blockIdx.x / ntiles;
    const int rb    = (blockIdx.x % ntiles) * 32;
    pout += (long)chunk * STEPS * nrows;

    const int t  = threadIdx.x;
    const int tr = t >> 4;
    const int tc = t & 15;

    float acc[4][4];
#pragma unroll
    for (int i = 0; i < 4; i++)
#pragma unroll
        for (int j = 0; j < 4; j++) acc[i][j] = 0.0f;

    const int k0 = chunk * KC;
    for (int kt = k0; kt < k0 + KC; kt += 32) {
#pragma unroll
        for (int i = 0; i < 2; i++) {
            int e   = t + i * 128;
            int row = e >> 3;
            int kq  = (e & 7) * 4;
            float4 wv = *(const float4*)&W[(long)(rb + row) * 1024 + kt + kq];
            Ws[kq + 0][row] = wv.x;
            Ws[kq + 1][row] = wv.y;
            Ws[kq + 2][row] = wv.z;
            Ws[kq + 3][row] = wv.w;
        }
#pragma unroll
        for (int i = 0; i < 4; i++) {
            int e  = t + i * 128;
            int s  = e >> 3;
            int kq = (e & 7) * 4;
            float4 xv = *(const float4*)&X[xbase + (long)s * xstride + kt + kq];
            Xs[kq + 0][s] = xv.x;
            Xs[kq + 1][s] = xv.y;
            Xs[kq + 2][s] = xv.z;
            Xs[kq + 3][s] = xv.w;
        }
        __syncthreads();
#pragma unroll
        for (int k = 0; k < 32; k++) {
            float4 wv = *(const float4*)&Ws[k][tr * 4];
            float4 xv = *(const float4*)&Xs[k][tc * 4];
            acc[0][0] = fmaf(wv.x, xv.x, acc[0][0]);
            acc[0][1] = fmaf(wv.x, xv.y, acc[0][1]);
            acc[0][2] = fmaf(wv.x, xv.z, acc[0][2]);
            acc[0][3] = fmaf(wv.x, xv.w, acc[0][3]);
            acc[1][0] = fmaf(wv.y, xv.x, acc[1][0]);
            acc[1][1] = fmaf(wv.y, xv.y, acc[1][1]);
            acc[1][2] = fmaf(wv.y, xv.z, acc[1][2]);
            acc[1][3] = fmaf(wv.y, xv.w, acc[1][3]);
            acc[2][0] = fmaf(wv.z, xv.x, acc[2][0]);
            acc[2][1] = fmaf(wv.z, xv.y, acc[2][1]);
            acc[2][2] = fmaf(wv.z, xv.z, acc[2][2]);
            acc[2][3] = fmaf(wv.z, xv.w, acc[2][3]);
            acc[3][0] = fmaf(wv.w, xv.x, acc[3][0]);
            acc[3][1] = fmaf(wv.w, xv.y, acc[3][1]);
            acc[3][2] = fmaf(wv.w, xv.z, acc[3][2]);
            acc[3][3] = fmaf(wv.w, xv.w, acc[3][3]);
        }
        __syncthreads();
    }

#pragma unroll
    for (int i = 0; i < 4; i++) {
        int row = rb + tr * 4 + i;
#pragma unroll
        for (int j = 0; j < 4; j++)
            pout[(long)(tc * 4 + j) * nrows + row] = acc[i][j];
    }
}

// ============================================================
// Persistent LSTM recurrence. 128 CTAs x 256 threads.
// - Whh in registers as packed f32x2
// - h exchange: sentinel-polled data via relaxed gpu-scope atomics
// ============================================================
__global__ __launch_bounds__(256, 1)
void lstm_rec(const float* __restrict__ Whh,
              const float* __restrict__ ba, const float* __restrict__ bb,
              int layer)
{
    __shared__ __align__(16) float hsh[HID];
    __shared__ float graw[32];   // [unit*4 + gate]
    __shared__ float gact[32];

    float* hseq = layer ? g_h2 : g_h1;
    const int r    = blockIdx.x;
    const int t    = threadIdx.x;
    const int lane = t & 31;
    const int w    = t >> 5;
    const int g    = w & 3;
    const int jh   = w >> 2;
    const int rowbase = (g << 10) + (r << 3) + (jh << 2);

    // packed weights: w{q}[p] covers columns p*64 + lane*2 + {0,1}
    ull w0[16], w1[16], w2[16], w3[16];
#pragma unroll
    for (int p = 0; p < 16; p++) {
        long o = (long)rowbase * 1024 + p * 64 + lane * 2;
        w0[p] = *(const ull*)(Whh + o);
        w1[p] = *(const ull*)(Whh + o + 1024);
        w2[p] = *(const ull*)(Whh + o + 2048);
        w3[p] = *(const ull*)(Whh + o + 3072);
    }
    float4 bias = make_float4(0.f, 0.f, 0.f, 0.f);
    if (lane == 0) {
        bias.x = ba[rowbase]     + bb[rowbase];
        bias.y = ba[rowbase + 1] + bb[rowbase + 1];
        bias.z = ba[rowbase + 2] + bb[rowbase + 2];
        bias.w = ba[rowbase + 3] + bb[rowbase + 3];
    }
    float creg = 0.0f;   // cell state (warp 0, lanes < 8)
    __syncthreads();

    for (int s = 0; s < STEPS; s++) {
        // xg = sum of 8 GEMM partials + bias (lane 0 per warp)
        float4 xq = bias;
        if (lane == 0) {
            long b = (long)s * G4 + rowbase;
#pragma unroll
            for (int c = 0; c < NCH; c++) {
                float4 p = *(const float4*)&g_xgp[b + (long)c * STEPS * G4];
                xq.x += p.x; xq.y += p.y; xq.z += p.z; xq.w += p.w;
            }
        }

        float a0 = 0.f, a1 = 0.f, a2 = 0.f, a3 = 0.f;
        if (s > 0) {
            // poll h_{s-1}: relaxed atomic loads, data itself is the flag
            const uint* src = (const uint*)(hseq + (s - 1) * HID) + t * 4;
            uint hx, hy, hz, hw;
            for (;;) {
                hx = ld_relaxed_u32(src);
                hy = ld_relaxed_u32(src + 1);
                hz = ld_relaxed_u32(src + 2);
                hw = ld_relaxed_u32(src + 3);
                if (hx != SENT && hy != SENT && hz != SENT && hw != SENT) break;
            }
            ((uint4*)hsh)[t] = make_uint4(hx, hy, hz, hw);
            __syncthreads();   // staging sync

            ull acc0 = 0ull, acc1 = 0ull, acc2 = 0ull, acc3 = 0ull;
#pragma unroll
            for (int p = 0; p < 16; p++) {
                ull h2 = *(const ull*)&hsh[p * 64 + lane * 2];
                acc0 = fma2(w0[p], h2, acc0);
                acc1 = fma2(w1[p], h2, acc1);
                acc2 = fma2(w2[p], h2, acc2);
                acc3 = fma2(w3[p], h2, acc3);
            }
            float2 f0 = unpack2(acc0), f1 = unpack2(acc1), f2 = unpack2(acc2), f3 = unpack2(acc3);
            a0 = f0.x + f0.y; a1 = f1.x + f1.y; a2 = f2.x + f2.y; a3 = f3.x + f3.y;
#pragma unroll
            for (int o = 16; o > 0; o >>= 1) {
                a0 += __shfl_down_sync(0xffffffffu, a0, o);
                a1 += __shfl_down_sync(0xffffffffu, a1, o);
                a2 += __shfl_down_sync(0xffffffffu, a2, o);
                a3 += __shfl_down_sync(0xffffffffu, a3, o);
            }
        }

        if (lane == 0) {
            graw[(jh * 4 + 0) * 4 + g] = a0 + xq.x;
            graw[(jh * 4 + 1) * 4 + g] = a1 + xq.y;
            graw[(jh * 4 + 2) * 4 + g] = a2 + xq.z;
            graw[(jh * 4 + 3) * 4 + g] = a3 + xq.w;
        }
        __syncthreads();   // (A)

        if (w == 0) {
            float v = graw[lane];                       // lane = unit*4 + gate
            gact[lane] = ((lane & 3) == 2) ? tanhfast(v) : sigf(v);
            __syncwarp();
            if (lane < 8) {
                float iv = gact[lane * 4 + 0];
                float fv = gact[lane * 4 + 1];
                float gv = gact[lane * 4 + 2];
                float ov = gact[lane * 4 + 3];
                creg = fmaf(fv, creg, iv * gv);
                st_relaxed_f32(&hseq[s * HID + r * 8 + lane], ov * tanhfast(creg));
            }
        }
        __syncthreads();   // end-of-step (matches proven R5 barrier structure)
    }
}

// ============================================================
// FC2 fused with fc1 partial-reduce + bias + ReLU. One CTA per s.
// ============================================================
__global__ __launch_bounds__(128)
void fc2_k(const float* __restrict__ W2, const float* __restrict__ b2,
           const float* __restrict__ b1, float* __restrict__ out)
{
    __shared__ __align__(16) float zsh[512];
    const int s = blockIdx.x;
    const int t = threadIdx.x, lane = t & 31, w = t >> 5;

    {
        const long base = (long)s * 512 + t * 4;
        float4 z = *(const float4*)&b1[t * 4];
#pragma unroll
        for (int c = 0; c < NCH; c++) {
            float4 p = *(const float4*)&g_zp[base + (long)c * STEPS * 512];
            z.x += p.x; z.y += p.y; z.z += p.z; z.w += p.w;
        }
        z.x = fmaxf(z.x, 0.f); z.y = fmaxf(z.y, 0.f);
        z.z = fmaxf(z.z, 0.f); z.w = fmaxf(z.w, 0.f);
        *(float4*)&zsh[t * 4] = z;
    }
    __syncthreads();

    for (int c = w; c < CC; c += 4) {
        float acc = 0.f;
#pragma unroll
        for (int k = 0; k < 16; k++)
            acc = fmaf(zsh[k * 32 + lane], W2[c * 512 + k * 32 + lane], acc);
#pragma unroll
        for (int o = 16; o > 0; o >>= 1)
            acc += __shfl_down_sync(0xffffffffu, acc, o);
        if (lane == 0) out[s * CC + c] = acc + b2[c];
    }
}

// ============================================================
extern "C" void kernel_launch(void* const* d_in, const int* in_sizes, int n_in,
                              void* d_out, int out_size)
{
    const float* x    = (const float*)d_in[0];
    const float* Wih0 = (const float*)d_in[1];
    const float* Whh0 = (const float*)d_in[2];
    const float* bih0 = (const float*)d_in[3];
    const float* bhh0 = (const float*)d_in[4];
    const float* Wih1 = (const float*)d_in[5];
    const float* Whh1 = (const float*)d_in[6];
    const float* bih1 = (const float*)d_in[7];
    const float* bhh1 = (const float*)d_in[8];
    const float* W1   = (const float*)d_in[9];
    const float* b1   = (const float*)d_in[10];
    const float* W2   = (const float*)d_in[11];
    const float* b2   = (const float*)d_in[12];
    float* out = (float*)d_out;

    reset_kernel<<<256, 256>>>();                 // sentinel-fill h buffers
    gemm8_k<<<1024, 128>>>(0, x, Wih0);           // xg partials, layer 1
    lstm_rec<<<NB, 256>>>(Whh0, bih0, bhh0, 0);
    gemm8_k<<<1024, 128>>>(1, nullptr, Wih1);     // xg partials, layer 2
    lstm_rec<<<NB, 256>>>(Whh1, bih1, bhh1, 1);
    gemm8_k<<<128, 128>>>(2, nullptr, W1);        // fc1 partials
    fc2_k<<<64, 128>>>(W2, b2, b1, out);          // reduce+relu+fc2
}

// round 8
// speedup vs baseline: 1.6268x; 1.0677x over previous
#include <cuda_runtime.h>

// Shapes: seq=64 steps (orig B), only batch-row t=255 of T=256 matters.
#define STEPS 64
#define HID   1024
#define G4    4096
#define TT    256
#define DD    1024
#define CC    27
#define NB    128          // recurrence CTAs (1/SM, co-resident)
#define NCH   16           // GEMM K-split chunks
#define KC    64           // k per chunk
#define SENT  0xFFC0DEADu  // NaN payload: impossible LSTM output bit pattern

typedef unsigned long long ull;
typedef unsigned int uint;

// ---- scratch (device globals; no allocation) ----
__device__ __align__(16) float g_xgp[(long)NCH * STEPS * G4];  // gate-preact partials
__device__ __align__(16) float g_h1 [STEPS * HID];
__device__ __align__(16) float g_h2 [STEPS * HID];
__device__ __align__(16) float g_zp [NCH * STEPS * 512];       // fc1 partials

__global__ void reset_kernel() {
    int i = blockIdx.x * 256 + threadIdx.x;   // 256x256 = 65536 = STEPS*HID
    ((uint*)g_h1)[i] = SENT;
    ((uint*)g_h2)[i] = SENT;
}

__device__ __forceinline__ float sigf(float x)     { return 1.0f / (1.0f + __expf(-x)); }
__device__ __forceinline__ float tanhfast(float x) { return 2.0f / (1.0f + __expf(-2.0f * x)) - 1.0f; }

__device__ __forceinline__ ull fma2(ull a, ull b, ull c) {
    ull d;
    asm("fma.rn.f32x2 %0, %1, %2, %3;" : "=l"(d) : "l"(a), "l"(b), "l"(c));
    return d;
}
__device__ __forceinline__ float2 unpack2(ull v) {
    float2 f;
    asm("mov.b64 {%0, %1}, %2;" : "=f"(f.x), "=f"(f.y) : "l"(v));
    return f;
}
__device__ __forceinline__ ull bcast2(float f) {
    ull r;
    asm("mov.b64 %0, {%1, %1};" : "=l"(r) : "f"(f));
    return r;
}
// morally-strong relaxed atomics (gpu scope) for the racing h exchange
__device__ __forceinline__ ull ld_relaxed_b64(const ull* p) {
    ull v;
    asm volatile("ld.relaxed.gpu.global.b64 %0, [%1];" : "=l"(v) : "l"(p) : "memory");
    return v;
}
__device__ __forceinline__ void st_relaxed_f32(float* p, float v) {
    asm volatile("st.relaxed.gpu.global.f32 [%0], %1;" :: "l"(p), "f"(v) : "memory");
}

// ============================================================
// K-split (x16) tiled GEMM, float4 loads, f32x2 FMA, partials only:
//   mode 0: X = x[:,255,:] (stride T*D), rows=4096 -> g_xgp   grid 2048
//   mode 1: X = g_h1,                    rows=4096 -> g_xgp   grid 2048
//   mode 2: X = g_h2,                    rows=512  -> g_zp    grid 256
// ============================================================
__global__ __launch_bounds__(128)
void gemm16_k(int mode, const float* __restrict__ xin, const float* __restrict__ W)
{
    __shared__ __align__(16) float Ws[32][36];
    __shared__ __align__(16) float Xs[32][68];

    const float* X;
    long xbase, xstride;
    float* pout;
    int nrows, ntiles;
    if (mode == 0)      { X = xin;  xbase = 255L * DD; xstride = (long)TT * DD; pout = g_xgp; nrows = G4;  ntiles = 128; }
    else if (mode == 1) { X = g_h1; xbase = 0;         xstride = HID;           pout = g_xgp; nrows = G4;  ntiles = 128; }
    else                { X = g_h2; xbase = 0;         xstride = HID;           pout = g_zp;  nrows = 512; ntiles = 16;  }

    const int chunk = blockIdx.x / ntiles;
    const int rb    = (blockIdx.x % ntiles) * 32;
    pout += (long)chunk * STEPS * nrows;

    const int t  = threadIdx.x;
    const int tr = t >> 4;
    const int tc = t & 15;

    ull acc2[4][2];   // [row][col-pair], packed f32x2
#pragma unroll
    for (int i = 0; i < 4; i++) { acc2[i][0] = 0ull; acc2[i][1] = 0ull; }

    const int k0 = chunk * KC;
    for (int kt = k0; kt < k0 + KC; kt += 32) {
#pragma unroll
        for (int i = 0; i < 2; i++) {
            int e   = t + i * 128;
            int row = e >> 3;
            int kq  = (e & 7) * 4;
            float4 wv = *(const float4*)&W[(long)(rb + row) * 1024 + kt + kq];
            Ws[kq + 0][row] = wv.x;
            Ws[kq + 1][row] = wv.y;
            Ws[kq + 2][row] = wv.z;
            Ws[kq + 3][row] = wv.w;
        }
#pragma unroll
        for (int i = 0; i < 4; i++) {
            int e  = t + i * 128;
            int s  = e >> 3;
            int kq = (e & 7) * 4;
            float4 xv = *(const float4*)&X[xbase + (long)s * xstride + kt + kq];
            Xs[kq + 0][s] = xv.x;
            Xs[kq + 1][s] = xv.y;
            Xs[kq + 2][s] = xv.z;
            Xs[kq + 3][s] = xv.w;
        }
        __syncthreads();
#pragma unroll
        for (int k = 0; k < 32; k++) {
            float4 wv = *(const float4*)&Ws[k][tr * 4];
            ull xp0 = *(const ull*)&Xs[k][tc * 4];       // (x0,x1)
            ull xp1 = *(const ull*)&Xs[k][tc * 4 + 2];   // (x2,x3)
            ull wb0 = bcast2(wv.x), wb1 = bcast2(wv.y);
            ull wb2 = bcast2(wv.z), wb3 = bcast2(wv.w);
            acc2[0][0] = fma2(wb0, xp0, acc2[0][0]);
            acc2[0][1] = fma2(wb0, xp1, acc2[0][1]);
            acc2[1][0] = fma2(wb1, xp0, acc2[1][0]);
            acc2[1][1] = fma2(wb1, xp1, acc2[1][1]);
            acc2[2][0] = fma2(wb2, xp0, acc2[2][0]);
            acc2[2][1] = fma2(wb2, xp1, acc2[2][1]);
            acc2[3][0] = fma2(wb3, xp0, acc2[3][0]);
            acc2[3][1] = fma2(wb3, xp1, acc2[3][1]);
        }
        __syncthreads();
    }

#pragma unroll
    for (int i = 0; i < 4; i++) {
        int row = rb + tr * 4 + i;
#pragma unroll
        for (int jp = 0; jp < 2; jp++) {
            float2 v = unpack2(acc2[i][jp]);
            pout[(long)(tc * 4 + jp * 2 + 0) * nrows + row] = v.x;
            pout[(long)(tc * 4 + jp * 2 + 1) * nrows + row] = v.y;
        }
    }
}

// ============================================================
// Persistent LSTM recurrence. 128 CTAs x 512 threads (16 warps).
// Warp w: gate g=w&3, unit-pair jh=w>>2 -> rows rowbase, rowbase+1.
// Whh rows in registers (packed f32x2). h exchange: sentinel-polled
// relaxed b64 atomics. 2 syncthreads/step.
// ============================================================
__global__ __launch_bounds__(512, 1)
void lstm_rec(const float* __restrict__ Whh,
              const float* __restrict__ ba, const float* __restrict__ bb,
              int layer)
{
    __shared__ __align__(16) float hsh[HID];
    __shared__ float graw[32];   // [unit*4 + gate]
    __shared__ float gact[32];

    float* hseq = layer ? g_h2 : g_h1;
    const int r    = blockIdx.x;
    const int t    = threadIdx.x;
    const int lane = t & 31;
    const int w    = t >> 5;       // 0..15
    const int g    = w & 3;
    const int jh   = w >> 2;       // 0..3
    const int rowbase = (g << 10) + (r << 3) + (jh << 1);   // 2 rows

    // packed weights: w{q}[p] covers columns p*64 + lane*2 + {0,1} of row rowbase+q
    ull w0[16], w1[16];
#pragma unroll
    for (int p = 0; p < 16; p++) {
        long o = (long)rowbase * 1024 + p * 64 + lane * 2;
        w0[p] = *(const ull*)(Whh + o);
        w1[p] = *(const ull*)(Whh + o + 1024);
    }
    float2 bias = make_float2(0.f, 0.f);
    if (lane == 16) {
        bias.x = ba[rowbase]     + bb[rowbase];
        bias.y = ba[rowbase + 1] + bb[rowbase + 1];
    }
    float creg = 0.0f;   // cell state (warp 0, lanes < 8)
    __syncthreads();

    for (int s = 0; s < STEPS; s++) {
        // xg partials: lanes 0..15 each load one chunk's float2 (summed via
        // the shuffle reduce below); lane 16 contributes the bias.
        float2 part = make_float2(0.f, 0.f);
        if (lane < NCH)
            part = *(const float2*)&g_xgp[(long)lane * STEPS * G4 + (long)s * G4 + rowbase];
        else if (lane == 16)
            part = bias;

        float a0 = part.x, a1 = part.y;
        if (s > 0) {
            // poll h_{s-1}: one relaxed b64 per thread; data itself is the flag
            const ull* src = (const ull*)(hseq + (s - 1) * HID) + t;
            ull hv;
            uint2 u;
            do {
                hv = ld_relaxed_b64(src);
                u  = *(uint2*)&hv;
            } while (u.x == SENT || u.y == SENT);
            ((ull*)hsh)[t] = hv;
            __syncthreads();   // staging sync

            ull acc0 = 0ull, acc1 = 0ull;
#pragma unroll
            for (int p = 0; p < 16; p++) {
                ull h2 = *(const ull*)&hsh[p * 64 + lane * 2];
                acc0 = fma2(w0[p], h2, acc0);
                acc1 = fma2(w1[p], h2, acc1);
            }
            float2 f0 = unpack2(acc0), f1 = unpack2(acc1);
            a0 += f0.x + f0.y;
            a1 += f1.x + f1.y;
        }
#pragma unroll
        for (int o = 16; o > 0; o >>= 1) {
            a0 += __shfl_down_sync(0xffffffffu, a0, o);
            a1 += __shfl_down_sync(0xffffffffu, a1, o);
        }
        if (lane == 0) {
            graw[(jh * 2 + 0) * 4 + g] = a0;
            graw[(jh * 2 + 1) * 4 + g] = a1;
        }
        __syncthreads();   // (A)

        if (w == 0) {
            float v = graw[lane];                       // lane = unit*4 + gate
            gact[lane] = ((lane & 3) == 2) ? tanhfast(v) : sigf(v);
            __syncwarp();
            if (lane < 8) {
                float iv = gact[lane * 4 + 0];
                float fv = gact[lane * 4 + 1];
                float gv = gact[lane * 4 + 2];
                float ov = gact[lane * 4 + 3];
                creg = fmaf(fv, creg, iv * gv);
                st_relaxed_f32(&hseq[s * HID + r * 8 + lane], ov * tanhfast(creg));
            }
        }
        // no end-of-step sync:
        //  - hsh(s+1) writes are gated by poll success, which requires warp 0's
        //    h[s] store, which follows all GEMV reads of hsh(s).
        //  - graw(s+1) writes follow the staging sync, which warp 0 joins only
        //    after its graw(s)/gact reads.
    }
}

// ============================================================
// FC2 fused with fc1 partial-reduce + bias + ReLU. One CTA per s.
// ============================================================
__global__ __launch_bounds__(128)
void fc2_k(const float* __restrict__ W2, const float* __restrict__ b2,
           const float* __restrict__ b1, float* __restrict__ out)
{
    __shared__ __align__(16) float zsh[512];
    const int s = blockIdx.x;
    const int t = threadIdx.x, lane = t & 31, w = t >> 5;

    {
        const long base = (long)s * 512 + t * 4;
        float4 z = *(const float4*)&b1[t * 4];
#pragma unroll
        for (int c = 0; c < NCH; c++) {
            float4 p = *(const float4*)&g_zp[base + (long)c * STEPS * 512];
            z.x += p.x; z.y += p.y; z.z += p.z; z.w += p.w;
        }
        z.x = fmaxf(z.x, 0.f); z.y = fmaxf(z.y, 0.f);
        z.z = fmaxf(z.z, 0.f); z.w = fmaxf(z.w, 0.f);
        *(float4*)&zsh[t * 4] = z;
    }
    __syncthreads();

    for (int c = w; c < CC; c += 4) {
        float acc = 0.f;
#pragma unroll
        for (int k = 0; k < 16; k++)
            acc = fmaf(zsh[k * 32 + lane], W2[c * 512 + k * 32 + lane], acc);
#pragma unroll
        for (int o = 16; o > 0; o >>= 1)
            acc += __shfl_down_sync(0xffffffffu, acc, o);
        if (lane == 0) out[s * CC + c] = acc + b2[c];
    }
}

// ============================================================
extern "C" void kernel_launch(void* const* d_in, const int* in_sizes, int n_in,
                              void* d_out, int out_size)
{
    const float* x    = (const float*)d_in[0];
    const float* Wih0 = (const float*)d_in[1];
    const float* Whh0 = (const float*)d_in[2];
    const float* bih0 = (const float*)d_in[3];
    const float* bhh0 = (const float*)d_in[4];
    const float* Wih1 = (const float*)d_in[5];
    const float* Whh1 = (const float*)d_in[6];
    const float* bih1 = (const float*)d_in[7];
    const float* bhh1 = (const float*)d_in[8];
    const float* W1   = (const float*)d_in[9];
    const float* b1   = (const float*)d_in[10];
    const float* W2   = (const float*)d_in[11];
    const float* b2   = (const float*)d_in[12];
    float* out = (float*)d_out;

    reset_kernel<<<256, 256>>>();                    // sentinel-fill h buffers
    gemm16_k<<<128 * NCH, 128>>>(0, x, Wih0);        // xg partials, layer 1
    lstm_rec<<<NB, 512>>>(Whh0, bih0, bhh0, 0);
    gemm16_k<<<128 * NCH, 128>>>(1, nullptr, Wih1);  // xg partials, layer 2
    lstm_rec<<<NB, 512>>>(Whh1, bih1, bhh1, 1);
    gemm16_k<<<16 * NCH, 128>>>(2, nullptr, W1);     // fc1 partials
    fc2_k<<<64, 128>>>(W2, b2, b1, out);             // reduce+relu+fc2
}